// round 8
// baseline (speedup 1.0000x reference)
#include <cuda_runtime.h>
#include <cstdint>

typedef unsigned long long ull;

#define BATCH 4
#define NC    64
#define CI    32
#define NPIX  6400
#define BM    64
#define BN    64

// Scratch (no allocations allowed in kernel_launch)
__device__ float g_theta[BATCH * CI * NPIX];
__device__ float g_phi  [BATCH * CI * NPIX];
__device__ float g_gx   [BATCH * CI * NPIX];
__device__ float g_y    [BATCH * CI * NPIX];

// ---- packed f32x2 helpers (FFMA2 path: 2x FP32 FMA throughput on sm_103a) ----
__device__ __forceinline__ ull ffma2(ull a, ull b, ull c) {
    ull d; asm("fma.rn.f32x2 %0, %1, %2, %3;" : "=l"(d) : "l"(a), "l"(b), "l"(c)); return d;
}
__device__ __forceinline__ ull pack2(float lo, float hi) {
    ull d; asm("mov.b64 %0, {%1, %2};" : "=l"(d) : "f"(lo), "f"(hi)); return d;
}
__device__ __forceinline__ void unpack2(ull v, float& lo, float& hi) {
    asm("mov.b64 {%0, %1}, %2;" : "=f"(lo), "=f"(hi) : "l"(v));
}

// ---- cp.async helpers ----
__device__ __forceinline__ uint32_t sptr(const void* p) {
    return (uint32_t)__cvta_generic_to_shared(p);
}
__device__ __forceinline__ void cpa16(uint32_t dst, const void* src) {
    asm volatile("cp.async.cg.shared.global [%0], [%1], 16;" :: "r"(dst), "l"(src));
}
__device__ __forceinline__ void cpa_commit() { asm volatile("cp.async.commit_group;" ::: "memory"); }
__device__ __forceinline__ void cpa_wait0()  { asm volatile("cp.async.wait_group 0;"  ::: "memory"); }

// ============================================================================
// Kernel 1: theta/phi/g 1x1 convs. 128 threads/block, 200 blocks. x row cached
// in packed f32x2 registers; FFMA2 inner products. Outputs [b][d][n] d-major.
// ============================================================================
__global__ void __launch_bounds__(128) front_kernel(
    const float* __restrict__ x,
    const float* __restrict__ wt, const float* __restrict__ bt,
    const float* __restrict__ wp, const float* __restrict__ bp,
    const float* __restrict__ wg, const float* __restrict__ bg)
{
    __shared__ float ws[3][CI][NC];     // pair-readable as ull (row contiguous)
    __shared__ float bs[3][CI];
    int tid = threadIdx.x;
    for (int i = tid; i < 3 * CI * NC; i += 128) {
        int m = i / (CI * NC), r = i % (CI * NC);
        const float* w = (m == 0) ? wt : ((m == 1) ? wp : wg);
        ws[m][r / NC][r % NC] = w[r];
    }
    if (tid < 3 * CI) {
        int m = tid / CI, o = tid % CI;
        bs[m][o] = (m == 0) ? bt[o] : ((m == 1) ? bp[o] : bg[o]);
    }
    __syncthreads();

    int gn = blockIdx.x * 128 + tid;
    int b = gn / NPIX, n = gn % NPIX;

    ull xr2[NC / 2];
#pragma unroll
    for (int c2 = 0; c2 < NC / 2; c2++) {
        float a = x[(b * NC + 2 * c2)     * NPIX + n];
        float c = x[(b * NC + 2 * c2 + 1) * NPIX + n];
        xr2[c2] = pack2(a, c);
    }

    float* outs[3] = { g_theta, g_phi, g_gx };
#pragma unroll
    for (int m = 0; m < 3; m++) {
        for (int o = 0; o < CI; o++) {
            const ull* wrow = (const ull*)&ws[m][o][0];
            ull acc2 = 0ull;
#pragma unroll
            for (int c2 = 0; c2 < NC / 2; c2++) acc2 = ffma2(wrow[c2], xr2[c2], acc2);
            float hi, lo; unpack2(acc2, lo, hi);
            outs[m][(b * CI + o) * NPIX + n] = bs[m][o] + lo + hi;
        }
    }
}

// ============================================================================
// Kernel 2: attention, NO-MAX softmax (logits bounded ~35 -> exp safe in fp32).
// 256 threads as 16x16. Double-buffered K/V tiles via cp.async; 2 syncs/iter.
// l accumulated privately per thread, reduced once at the end.
// Dynamic smem 64KB: qs2 16K | ks[2] 16K | vs[2] 16K | ps2 16K
// ============================================================================
__global__ void __launch_bounds__(256) attn_kernel()
{
    extern __shared__ char smem_raw[];
    ull   (*qs2)     = (ull*)(smem_raw);                        // [CI][BM] dup pairs
    float (*ksb)[CI][BN] = (float(*)[CI][BN])(smem_raw + 16384);// 2 buffers
    float (*vsb)[CI][BN] = (float(*)[CI][BN])(smem_raw + 32768);// 2 buffers (swizzled)
    ull   (*ps2)[BN / 2] = (ull(*)[BN / 2])(smem_raw + 49152);  // P as c-pairs

    int tid = threadIdx.x;
    int ty = tid >> 4, tx = tid & 15;
    int b  = blockIdx.y;
    int n0 = blockIdx.x * BM;

    const float* theta = g_theta + b * CI * NPIX;
    const float* phi   = g_phi   + b * CI * NPIX;
    const float* gx    = g_gx    + b * CI * NPIX;

    // Q tile: loaded once, duplicated pairs
    for (int i = tid; i < CI * BM; i += 256) {
        int k = i >> 6, r = i & 63;
        float v = theta[k * NPIX + n0 + r];
        qs2[k * BM + r] = pack2(v, v);
    }

    // prologue: tile 0 into buffer 0 (4 cp.async chunks per thread)
#pragma unroll
    for (int h = 0; h < 2; h++) {
        int ch = tid + h * 256;                 // 0..511
        int k = ch >> 4, c4 = ch & 15;
        cpa16(sptr(&ksb[0][k][c4 * 4]), phi + k * NPIX + 0 + c4 * 4);
        int slot = c4 ^ ((k >> 1) & 7);
        cpa16(sptr(&vsb[0][k][slot * 4]), gx + k * NPIX + 0 + c4 * 4);
    }
    cpa_commit();

    float l[4];
    ull acc_o[4][2];
#pragma unroll
    for (int j = 0; j < 4; j++) { l[j] = 0.0f; acc_o[j][0] = 0ull; acc_o[j][1] = 0ull; }

    cpa_wait0();
    __syncthreads();

    for (int it = 0; it < NPIX / BN; it++) {
        int buf = it & 1;
        const float (*ks)[BN] = ksb[buf];
        const float (*vs)[BN] = vsb[buf];

        // ---- S = Q K^T ----
        ull acc_s[4][2];
#pragma unroll
        for (int j = 0; j < 4; j++) { acc_s[j][0] = 0ull; acc_s[j][1] = 0ull; }
#pragma unroll
        for (int k = 0; k < CI; k++) {
            ulonglong2 qa = *(const ulonglong2*)&qs2[k * BM + 4 * ty];
            ulonglong2 qb = *(const ulonglong2*)&qs2[k * BM + 4 * ty + 2];
            ulonglong2 bv = *(const ulonglong2*)&ks[k][4 * tx];
            acc_s[0][0] = ffma2(qa.x, bv.x, acc_s[0][0]);
            acc_s[0][1] = ffma2(qa.x, bv.y, acc_s[0][1]);
            acc_s[1][0] = ffma2(qa.y, bv.x, acc_s[1][0]);
            acc_s[1][1] = ffma2(qa.y, bv.y, acc_s[1][1]);
            acc_s[2][0] = ffma2(qb.x, bv.x, acc_s[2][0]);
            acc_s[2][1] = ffma2(qb.x, bv.y, acc_s[2][1]);
            acc_s[3][0] = ffma2(qb.y, bv.x, acc_s[3][0]);
            acc_s[3][1] = ffma2(qb.y, bv.y, acc_s[3][1]);
        }

        __syncthreads();   // all threads done with PV of prev iter (ps2 + kv[buf^1] free)

        // prefetch next tile into the other buffer (overlaps with exp/P-store)
        if (it + 1 < NPIX / BN) {
            int c0n = (it + 1) * BN;
#pragma unroll
            for (int h = 0; h < 2; h++) {
                int ch = tid + h * 256;
                int k = ch >> 4, c4 = ch & 15;
                cpa16(sptr(&ksb[buf ^ 1][k][c4 * 4]), phi + k * NPIX + c0n + c4 * 4);
                int slot = c4 ^ ((k >> 1) & 7);
                cpa16(sptr(&vsb[buf ^ 1][k][slot * 4]), gx + k * NPIX + c0n + c4 * 4);
            }
        }
        cpa_commit();

        // ---- softmax numerator: p = exp(s) directly (no max, no shfl) ----
#pragma unroll
        for (int j = 0; j < 4; j++) {
            float s0, s1, s2, s3;
            unpack2(acc_s[j][0], s0, s1);
            unpack2(acc_s[j][1], s2, s3);
            float p0 = __expf(s0), p1 = __expf(s1);
            float p2 = __expf(s2), p3 = __expf(s3);
            l[j] += (p0 + p1) + (p2 + p3);
            ulonglong2 pw; pw.x = pack2(p0, p1); pw.y = pack2(p2, p3);
            *(ulonglong2*)&ps2[4 * ty + j][2 * tx] = pw;   // STS.128
        }

        cpa_wait0();
        __syncthreads();   // ps2 + next kv visible

        // ---- O += P V (c-parity pairs) ----
        int d0 = 2 * tx;
#pragma unroll
        for (int cg = 0; cg < 16; cg++) {
            int slot = cg ^ (tx & 7);
            ulonglong2 v0 = *(const ulonglong2*)&vs[d0][slot << 2];
            ulonglong2 v1 = *(const ulonglong2*)&vs[d0 + 1][slot << 2];
#pragma unroll
            for (int j = 0; j < 4; j++) {
                ulonglong2 pp = *(const ulonglong2*)&ps2[4 * ty + j][2 * cg]; // broadcast
                acc_o[j][0] = ffma2(pp.x, v0.x, acc_o[j][0]);
                acc_o[j][0] = ffma2(pp.y, v0.y, acc_o[j][0]);
                acc_o[j][1] = ffma2(pp.x, v1.x, acc_o[j][1]);
                acc_o[j][1] = ffma2(pp.y, v1.y, acc_o[j][1]);
            }
        }
    }

    __syncthreads();       // last PV done before reusing ps2 as scratch

    // ---- reduce l across the 16 tx lanes (once for the whole kernel) ----
#pragma unroll
    for (int j = 0; j < 4; j++) {
#pragma unroll
        for (int o = 1; o < 16; o <<= 1) l[j] += __shfl_xor_sync(0xffffffffu, l[j], o);
    }

    // ---- finalize: horizontal add of c-parity, /l, transpose via smem ----
    float* os = (float*)ps2;           // os[d][r], stride BM
#pragma unroll
    for (int j = 0; j < 4; j++) {
        float inv = 1.0f / l[j];
        float a0, a1, b0, b1;
        unpack2(acc_o[j][0], a0, a1);
        unpack2(acc_o[j][1], b0, b1);
        os[(2 * tx)     * BM + 4 * ty + j] = (a0 + a1) * inv;
        os[(2 * tx + 1) * BM + 4 * ty + j] = (b0 + b1) * inv;
    }
    __syncthreads();
    float* y = g_y + b * CI * NPIX;
    for (int i = tid; i < CI * BM; i += 256) {
        int d = i >> 6, r = i & 63;
        y[d * NPIX + n0 + r] = os[d * BM + r];   // coalesced
    }
}

// ============================================================================
// Kernel 3: out conv (32->64) + BN (folded) + residual. 128 thr, y in regs,
// FFMA2 inner products.
// ============================================================================
__global__ void __launch_bounds__(128) back_kernel(
    const float* __restrict__ x,
    const float* __restrict__ w_out, const float* __restrict__ b_out,
    const float* __restrict__ gamma, const float* __restrict__ beta,
    const float* __restrict__ mean,  const float* __restrict__ var,
    float* __restrict__ out)
{
    __shared__ float ws[NC][CI];       // pair-readable as ull
    __shared__ float invs[NC], shift[NC];
    int tid = threadIdx.x;

    for (int i = tid; i < NC * CI; i += 128) ws[i / CI][i % CI] = w_out[i];
    if (tid < NC) {
        float inv = gamma[tid] * rsqrtf(var[tid] + 1e-4f);
        invs[tid]  = inv;
        shift[tid] = beta[tid] + (b_out[tid] - mean[tid]) * inv;
    }
    __syncthreads();

    int b  = blockIdx.y;
    int n  = blockIdx.x * 128 + tid;

    ull yr2[CI / 2];
#pragma unroll
    for (int d2 = 0; d2 < CI / 2; d2++) {
        float a = g_y[(b * CI + 2 * d2)     * NPIX + n];
        float c = g_y[(b * CI + 2 * d2 + 1) * NPIX + n];
        yr2[d2] = pack2(a, c);
    }

    for (int co = 0; co < NC; co++) {
        const ull* wrow = (const ull*)&ws[co][0];
        ull acc2 = 0ull;
#pragma unroll
        for (int d2 = 0; d2 < CI / 2; d2++) acc2 = ffma2(wrow[d2], yr2[d2], acc2);
        float hi, lo; unpack2(acc2, lo, hi);
        int idx = (b * NC + co) * NPIX + n;
        out[idx] = (lo + hi) * invs[co] + shift[co] + x[idx];
    }
}

// ============================================================================
extern "C" void kernel_launch(void* const* d_in, const int* in_sizes, int n_in,
                              void* d_out, int out_size)
{
    const float* x       = (const float*)d_in[0];
    const float* w_theta = (const float*)d_in[1];
    const float* b_theta = (const float*)d_in[2];
    const float* w_phi   = (const float*)d_in[3];
    const float* b_phi   = (const float*)d_in[4];
    const float* w_g     = (const float*)d_in[5];
    const float* b_g     = (const float*)d_in[6];
    const float* w_out   = (const float*)d_in[7];
    const float* b_out   = (const float*)d_in[8];
    const float* bn_g    = (const float*)d_in[9];
    const float* bn_b    = (const float*)d_in[10];
    const float* bn_m    = (const float*)d_in[11];
    const float* bn_v    = (const float*)d_in[12];
    float* out = (float*)d_out;

    static bool attr_set = false;
    if (!attr_set) {
        cudaFuncSetAttribute(attn_kernel, cudaFuncAttributeMaxDynamicSharedMemorySize, 65536);
        attr_set = true;
    }

    front_kernel<<<(BATCH * NPIX) / 128, 128>>>(x, w_theta, b_theta, w_phi, b_phi, w_g, b_g);
    attn_kernel<<<dim3(NPIX / BM, BATCH), 256, 65536>>>();
    back_kernel<<<dim3(NPIX / 128, BATCH), 128>>>(x, w_out, b_out, bn_g, bn_b, bn_m, bn_v, out);
}

// round 10
// speedup vs baseline: 2.6402x; 2.6402x over previous
#include <cuda_runtime.h>
#include <cuda_bf16.h>
#include <cstdint>

typedef unsigned long long ull;

#define BATCH 4
#define NC    64
#define CI    32
#define NPIX  6400
#define BM    128          // q rows per CTA
#define BN    64           // k cols per tile
#define NT    (NPIX / BN)  // 100 k-tiles

// ---------------- scratch (__device__ globals; no allocs allowed) ----------
__device__ __align__(1024) __nv_bfloat16 g_tqn[BATCH * NPIX * 64]; // theta: [b][n][hi32|lo32]
__device__ __align__(1024) __nv_bfloat16 g_pqn[BATCH * NPIX * 64]; // phi:   [b][n][hi32|lo32]
__device__ __align__(1024) __nv_bfloat16 g_gxh[BATCH * CI * NPIX]; // g hi:  [b][d][n]
__device__ __align__(1024) __nv_bfloat16 g_gxl[BATCH * CI * NPIX]; // g lo:  [b][d][n]
__device__ float g_y[BATCH * CI * NPIX];                           // attention out [b][d][n]

// ---------------- small helpers -------------------------------------------
__device__ __forceinline__ ull ffma2(ull a, ull b, ull c) {
    ull d; asm("fma.rn.f32x2 %0, %1, %2, %3;" : "=l"(d) : "l"(a), "l"(b), "l"(c)); return d;
}
__device__ __forceinline__ ull pack2(float lo, float hi) {
    ull d; asm("mov.b64 %0, {%1, %2};" : "=l"(d) : "f"(lo), "f"(hi)); return d;
}
__device__ __forceinline__ void unpack2(ull v, float& lo, float& hi) {
    asm("mov.b64 {%0, %1}, %2;" : "=f"(lo), "=f"(hi) : "l"(v));
}
// packed bf16x2: low half <- lo, high half <- hi
__device__ __forceinline__ uint32_t bf16x2(float lo, float hi) {
    uint32_t r; asm("cvt.rn.bf16x2.f32 %0, %1, %2;" : "=r"(r) : "f"(hi), "f"(lo)); return r;
}
__device__ __forceinline__ uint32_t sptr(const void* p) {
    return (uint32_t)__cvta_generic_to_shared(p);
}
__device__ __forceinline__ void cpa16(uint32_t dst, const void* src) {
    asm volatile("cp.async.cg.shared.global [%0], [%1], 16;" :: "r"(dst), "l"(src));
}
__device__ __forceinline__ void cpa_commit() { asm volatile("cp.async.commit_group;" ::: "memory"); }
__device__ __forceinline__ void cpa_wait0()  { asm volatile("cp.async.wait_group 0;"  ::: "memory"); }
__device__ __forceinline__ uint32_t sw(uint32_t o) { return o ^ ((o >> 3) & 0x70); } // SW128

// ldmatrix x4 (16-bit tiles, non-transposed)
__device__ __forceinline__ void ldsm4(uint32_t* r, uint32_t addr) {
    asm volatile("ldmatrix.sync.aligned.m8n8.x4.shared.b16 {%0,%1,%2,%3}, [%4];"
                 : "=r"(r[0]), "=r"(r[1]), "=r"(r[2]), "=r"(r[3]) : "r"(addr));
}
// bf16 HMMA: D(16x8,f32) += A(16x16,bf16) * B(16x8,bf16)
__device__ __forceinline__ void mma16816(float* d, const uint32_t* a,
                                         uint32_t b0, uint32_t b1) {
    asm volatile(
        "mma.sync.aligned.m16n8k16.row.col.f32.bf16.bf16.f32 "
        "{%0,%1,%2,%3}, {%4,%5,%6,%7}, {%8,%9}, {%0,%1,%2,%3};"
        : "+f"(d[0]), "+f"(d[1]), "+f"(d[2]), "+f"(d[3])
        : "r"(a[0]), "r"(a[1]), "r"(a[2]), "r"(a[3]), "r"(b0), "r"(b1));
}

// ---------------- SMEM map -------------------------------------------------
#define SM_Q    0u       // 128 rows x 128B (hi|lo)               16384
#define SM_K0   16384u   // 64 x 128B per buf, stride 8192        16384 (x2)
#define SM_VH0  32768u   // 32 x 128B per buf, stride 8192
#define SM_VL0  36864u
#define SM_MISC 49152u   // larr: 2 x 128 floats = 1KB
#define SMEM_TOTAL (49152 + 1024)
// epilogue reuses SM_K0..SM_K0+32KB as os[2][32][128] floats

// ============================================================================
// Kernel 1: 1x1 convs -> bf16 hi/lo. theta/phi as [n][hi32|lo32] 128B rows
// (MMA operand layout); g as d-major hi/lo planes.
// ============================================================================
__global__ void __launch_bounds__(128) front_kernel(
    const float* __restrict__ x,
    const float* __restrict__ wt, const float* __restrict__ bt,
    const float* __restrict__ wp, const float* __restrict__ bp,
    const float* __restrict__ wg, const float* __restrict__ bg)
{
    __shared__ float ws[3][CI][NC];
    __shared__ float bs[3][CI];
    int tid = threadIdx.x;
    for (int i = tid; i < 3 * CI * NC; i += 128) {
        int m = i / (CI * NC), r = i % (CI * NC);
        const float* w = (m == 0) ? wt : ((m == 1) ? wp : wg);
        ws[m][r / NC][r % NC] = w[r];
    }
    if (tid < 3 * CI) {
        int m = tid / CI, o = tid % CI;
        bs[m][o] = (m == 0) ? bt[o] : ((m == 1) ? bp[o] : bg[o]);
    }
    __syncthreads();

    int gn = blockIdx.x * 128 + tid;
    int b = gn / NPIX, n = gn % NPIX;

    ull xr2[NC / 2];
#pragma unroll
    for (int c2 = 0; c2 < NC / 2; c2++) {
        float a = x[(b * NC + 2 * c2)     * NPIX + n];
        float c = x[(b * NC + 2 * c2 + 1) * NPIX + n];
        xr2[c2] = pack2(a, c);
    }

#pragma unroll
    for (int m = 0; m < 3; m++) {
        float v[CI];
        for (int o = 0; o < CI; o++) {
            const ull* wrow = (const ull*)&ws[m][o][0];
            ull acc2 = 0ull;
#pragma unroll
            for (int c2 = 0; c2 < NC / 2; c2++) acc2 = ffma2(wrow[c2], xr2[c2], acc2);
            float hi, lo; unpack2(acc2, lo, hi);
            v[o] = bs[m][o] + lo + hi;
        }
        if (m < 2) {
            uint32_t row[32];
#pragma unroll
            for (int o2 = 0; o2 < 16; o2++) {
                float a = v[2 * o2], c = v[2 * o2 + 1];
                uint32_t hp = bf16x2(a, c);
                row[o2] = hp;
                float ha = __uint_as_float(hp << 16);
                float hc = __uint_as_float(hp & 0xffff0000u);
                row[16 + o2] = bf16x2(a - ha, c - hc);
            }
            __nv_bfloat16* dst = ((m == 0) ? g_tqn : g_pqn) + (size_t)(b * NPIX + n) * 64;
            uint4* d4 = (uint4*)dst;
#pragma unroll
            for (int q = 0; q < 8; q++)
                d4[q] = make_uint4(row[4 * q], row[4 * q + 1], row[4 * q + 2], row[4 * q + 3]);
        } else {
#pragma unroll
            for (int o = 0; o < CI; o++) {
                __nv_bfloat16 h = __float2bfloat16(v[o]);
                size_t idx = (size_t)(b * CI + o) * NPIX + n;
                g_gxh[idx] = h;
                g_gxl[idx] = __float2bfloat16(v[o] - __bfloat162float(h));
            }
        }
    }
}

// ---------------- K/V tile loader (cp.async, SW128 dst) --------------------
__device__ __forceinline__ void load_kv(uint32_t sb, int buf,
                                        const __nv_bfloat16* pq,
                                        const __nv_bfloat16* vh,
                                        const __nv_bfloat16* vl,
                                        int c0, int tid)
{
    uint32_t kbase = sb + SM_K0 + (uint32_t)buf * 8192u;
#pragma unroll
    for (int h = 0; h < 2; h++) {
        int id = tid + h * 256;
        int k = id >> 3, ch = id & 7;
        cpa16(kbase + sw((uint32_t)(k * 128 + ch * 16)),
              pq + (size_t)(c0 + k) * 64 + ch * 8);
    }
    int d = tid >> 3, ch = tid & 7;
    uint32_t voff = sw((uint32_t)(d * 128 + ch * 16));
    cpa16(sb + SM_VH0 + (uint32_t)buf * 8192u + voff, vh + (size_t)d * NPIX + c0 + ch * 8);
    cpa16(sb + SM_VL0 + (uint32_t)buf * 8192u + voff, vl + (size_t)d * NPIX + c0 + ch * 8);
}

// ============================================================================
// Kernel 2: HMMA flash attention (no-max softmax; logits bounded ~35).
// 256 threads / 8 warps = 4 row-groups x 2 col-groups.
// Warp (rg,cg): S rows rg*32..+31, cols cg*32..+31. Split-bf16:
//   S = Qh*Kh + Qh*Kl + Ql*Kh ;  O += Ph*Vh + Ph*Vl + Pl*Vh
// P never leaves registers (S accum fragment == PV A fragment layout).
// ============================================================================
__global__ void __launch_bounds__(256) attn_kernel()
{
    extern __shared__ char smem[];
    uint32_t sb = sptr(smem);
    int tid = threadIdx.x;
    int w = tid >> 5, lid = tid & 31;
    int rg = w >> 1, cg = w & 1;
    int gid = lid >> 2, tig = lid & 3;
    int b = blockIdx.y;
    int n0pix = blockIdx.x * BM;

    const __nv_bfloat16* tq = g_tqn + (size_t)b * NPIX * 64;
    const __nv_bfloat16* pq = g_pqn + (size_t)b * NPIX * 64;
    const __nv_bfloat16* vh = g_gxh + (size_t)b * CI * NPIX;
    const __nv_bfloat16* vl = g_gxl + (size_t)b * CI * NPIX;

    // ---- prologue: Q tile + first K/V tile ----
#pragma unroll
    for (int h = 0; h < 4; h++) {
        int id = tid + h * 256;
        int r = id >> 3, ch = id & 7;
        cpa16(sb + SM_Q + sw((uint32_t)(r * 128 + ch * 16)),
              tq + (size_t)(n0pix + r) * 64 + ch * 8);
    }
    load_kv(sb, 0, pq, vh, vl, 0, tid);
    cpa_commit();
    cpa_wait0();
    __syncthreads();

    // ---- Q fragments (persistent): [mb][kstep][4], hi bytes 0-63, lo 64-127
    uint32_t qh[2][2][4], ql[2][2][4];
#pragma unroll
    for (int mb = 0; mb < 2; mb++) {
        uint32_t rowb = (uint32_t)(rg * 32 + mb * 16 + (lid & 15)) * 128 + (uint32_t)((lid >> 4) * 16);
#pragma unroll
        for (int ks = 0; ks < 2; ks++) {
            ldsm4(qh[mb][ks], sb + SM_Q + sw(rowb + (uint32_t)(ks * 32)));
            ldsm4(ql[mb][ks], sb + SM_Q + sw(rowb + (uint32_t)(64 + ks * 32)));
        }
    }

    float o[2][4][4];
    float lsum[2][2];
#pragma unroll
    for (int mb = 0; mb < 2; mb++) {
        lsum[mb][0] = 0.0f; lsum[mb][1] = 0.0f;
#pragma unroll
        for (int dn = 0; dn < 4; dn++)
#pragma unroll
            for (int e = 0; e < 4; e++) o[mb][dn][e] = 0.0f;
    }

    // per-lane ldmatrix address offsets (B tiles: 8 rows, 4 16B col-chunks)
    uint32_t blane = (uint32_t)((lid & 7) * 128 + (lid >> 3) * 16);

    for (int it = 0; it < NT; it++) {
        int buf = it & 1;
        if (it + 1 < NT) load_kv(sb, buf ^ 1, pq, vh, vl, (it + 1) * BN, tid);
        cpa_commit();

        uint32_t kb = sb + SM_K0 + (uint32_t)buf * 8192u;
        uint32_t vhb = sb + SM_VH0 + (uint32_t)buf * 8192u;
        uint32_t vlb = sb + SM_VL0 + (uint32_t)buf * 8192u;

        // ---- S = Q K^T (split-bf16) ----
        float sa[2][4][4];
#pragma unroll
        for (int mb = 0; mb < 2; mb++)
#pragma unroll
            for (int j = 0; j < 4; j++)
#pragma unroll
                for (int e = 0; e < 4; e++) sa[mb][j][e] = 0.0f;

#pragma unroll
        for (int j = 0; j < 4; j++) {
            uint32_t nrow = (uint32_t)((cg * 32 + j * 8) * 128);
            uint32_t kh[4], klr[4];
            ldsm4(kh,  kb + sw(nrow + blane));        // K hi, k0-31
            ldsm4(klr, kb + sw(nrow + 64u + blane));  // K lo, k0-31 (bytes 64-127)
#pragma unroll
            for (int mb = 0; mb < 2; mb++) {
                mma16816(sa[mb][j], qh[mb][0], kh[0],  kh[1]);   // hi*hi k0-15
                mma16816(sa[mb][j], qh[mb][1], kh[2],  kh[3]);   // hi*hi k16-31
                mma16816(sa[mb][j], qh[mb][0], klr[0], klr[1]);  // hi*lo
                mma16816(sa[mb][j], qh[mb][1], klr[2], klr[3]);
                mma16816(sa[mb][j], ql[mb][0], kh[0],  kh[1]);   // lo*hi
                mma16816(sa[mb][j], ql[mb][1], kh[2],  kh[3]);
            }
        }

        // ---- P = exp(S); pack split-bf16 A-fragments in registers ----
        uint32_t ph[2][2][4], pl[2][2][4];
#pragma unroll
        for (int mb = 0; mb < 2; mb++) {
#pragma unroll
            for (int j = 0; j < 4; j++) {
                float p0 = __expf(sa[mb][j][0]);
                float p1 = __expf(sa[mb][j][1]);
                float p2 = __expf(sa[mb][j][2]);
                float p3 = __expf(sa[mb][j][3]);
                lsum[mb][0] += p0 + p1;
                lsum[mb][1] += p2 + p3;
                int kc = j >> 1, rbase = (j & 1) * 2;
                uint32_t h0 = bf16x2(p0, p1);
                uint32_t h1 = bf16x2(p2, p3);
                ph[mb][kc][rbase]     = h0;
                ph[mb][kc][rbase + 1] = h1;
                float h0a = __uint_as_float(h0 << 16);
                float h0b = __uint_as_float(h0 & 0xffff0000u);
                float h1a = __uint_as_float(h1 << 16);
                float h1b = __uint_as_float(h1 & 0xffff0000u);
                pl[mb][kc][rbase]     = bf16x2(p0 - h0a, p1 - h0b);
                pl[mb][kc][rbase + 1] = bf16x2(p2 - h1a, p3 - h1b);
            }
        }

        // ---- O += P V (warp's k-range = m cols cg*32..+31 = bytes cg*64..) --
#pragma unroll
        for (int dn = 0; dn < 4; dn++) {
            uint32_t drow = (uint32_t)(dn * 8 * 128 + cg * 64);
            uint32_t vhf[4], vlf[4];
            ldsm4(vhf, vhb + sw(drow + blane));
            ldsm4(vlf, vlb + sw(drow + blane));
#pragma unroll
            for (int mb = 0; mb < 2; mb++) {
                mma16816(o[mb][dn], ph[mb][0], vhf[0], vhf[1]);  // Ph*Vh k0-15
                mma16816(o[mb][dn], ph[mb][1], vhf[2], vhf[3]);  // Ph*Vh k16-31
                mma16816(o[mb][dn], ph[mb][0], vlf[0], vlf[1]);  // Ph*Vl
                mma16816(o[mb][dn], ph[mb][1], vlf[2], vlf[3]);
                mma16816(o[mb][dn], pl[mb][0], vhf[0], vhf[1]);  // Pl*Vh
                mma16816(o[mb][dn], pl[mb][1], vhf[2], vhf[3]);
            }
        }

        cpa_wait0();
        __syncthreads();   // buf consumed by all; next buf resident
    }

    // ---- epilogue: reduce l (quad + cross-cg), combine O halves ----
    float* larr = (float*)(smem + SM_MISC);          // [2 cg][128]
    float* os   = (float*)(smem + SM_K0);            // [2 cg][32 d][128 r]

#pragma unroll
    for (int mb = 0; mb < 2; mb++) {
#pragma unroll
        for (int hf = 0; hf < 2; hf++) {
            float v = lsum[mb][hf];
            v += __shfl_xor_sync(0xffffffffu, v, 1);
            v += __shfl_xor_sync(0xffffffffu, v, 2);
            if (tig == 0)
                larr[cg * 128 + rg * 32 + mb * 16 + gid + 8 * hf] = v;
        }
    }

    float* osp = os + cg * 32 * 128;
#pragma unroll
    for (int mb = 0; mb < 2; mb++) {
        int row0 = rg * 32 + mb * 16 + gid;
#pragma unroll
        for (int dn = 0; dn < 4; dn++) {
            int d0 = dn * 8 + tig * 2;
            osp[d0 * 128 + row0]           = o[mb][dn][0];
            osp[(d0 + 1) * 128 + row0]     = o[mb][dn][1];
            osp[d0 * 128 + row0 + 8]       = o[mb][dn][2];
            osp[(d0 + 1) * 128 + row0 + 8] = o[mb][dn][3];
        }
    }
    __syncthreads();

    float* y = g_y + (size_t)b * CI * NPIX;
#pragma unroll
    for (int h = 0; h < 16; h++) {
        int idx = tid + h * 256;
        int d = idx >> 7, r = idx & 127;
        float denom = larr[r] + larr[128 + r];
        float num = os[d * 128 + r] + os[32 * 128 + d * 128 + r];
        y[(size_t)d * NPIX + n0pix + r] = num / denom;
    }
}

// ============================================================================
// Kernel 3: out conv (32->64) + BN (folded) + residual.
// ============================================================================
__global__ void __launch_bounds__(128) back_kernel(
    const float* __restrict__ x,
    const float* __restrict__ w_out, const float* __restrict__ b_out,
    const float* __restrict__ gamma, const float* __restrict__ beta,
    const float* __restrict__ mean,  const float* __restrict__ var,
    float* __restrict__ out)
{
    __shared__ float ws[NC][CI];
    __shared__ float invs[NC], shift[NC];
    int tid = threadIdx.x;

    for (int i = tid; i < NC * CI; i += 128) ws[i / CI][i % CI] = w_out[i];
    if (tid < NC) {
        float inv = gamma[tid] * rsqrtf(var[tid] + 1e-4f);
        invs[tid]  = inv;
        shift[tid] = beta[tid] + (b_out[tid] - mean[tid]) * inv;
    }
    __syncthreads();

    int b = blockIdx.y;
    int n = blockIdx.x * 128 + tid;

    ull yr2[CI / 2];
#pragma unroll
    for (int d2 = 0; d2 < CI / 2; d2++) {
        float a = g_y[(size_t)(b * CI + 2 * d2)     * NPIX + n];
        float c = g_y[(size_t)(b * CI + 2 * d2 + 1) * NPIX + n];
        yr2[d2] = pack2(a, c);
    }

    for (int co = 0; co < NC; co++) {
        const ull* wrow = (const ull*)&ws[co][0];
        ull acc2 = 0ull;
#pragma unroll
        for (int d2 = 0; d2 < CI / 2; d2++) acc2 = ffma2(wrow[d2], yr2[d2], acc2);
        float hi, lo; unpack2(acc2, lo, hi);
        int idx = (b * NC + co) * NPIX + n;
        out[idx] = (lo + hi) * invs[co] + shift[co] + x[idx];
    }
}

// ============================================================================
extern "C" void kernel_launch(void* const* d_in, const int* in_sizes, int n_in,
                              void* d_out, int out_size)
{
    const float* x       = (const float*)d_in[0];
    const float* w_theta = (const float*)d_in[1];
    const float* b_theta = (const float*)d_in[2];
    const float* w_phi   = (const float*)d_in[3];
    const float* b_phi   = (const float*)d_in[4];
    const float* w_g     = (const float*)d_in[5];
    const float* b_g     = (const float*)d_in[6];
    const float* w_out   = (const float*)d_in[7];
    const float* b_out   = (const float*)d_in[8];
    const float* bn_g    = (const float*)d_in[9];
    const float* bn_b    = (const float*)d_in[10];
    const float* bn_m    = (const float*)d_in[11];
    const float* bn_v    = (const float*)d_in[12];
    float* out = (float*)d_out;

    static bool attr_set = false;
    if (!attr_set) {
        cudaFuncSetAttribute(attn_kernel, cudaFuncAttributeMaxDynamicSharedMemorySize, SMEM_TOTAL);
        attr_set = true;
    }

    front_kernel<<<(BATCH * NPIX) / 128, 128>>>(x, w_theta, b_theta, w_phi, b_phi, w_g, b_g);
    attn_kernel<<<dim3(NPIX / BM, BATCH), 256, SMEM_TOTAL>>>();
    back_kernel<<<dim3(NPIX / 128, BATCH), 128>>>(x, w_out, b_out, bn_g, bn_b, bn_m, bn_v, out);
}